// round 7
// baseline (speedup 1.0000x reference)
#include <cuda_runtime.h>
#include <math.h>

#define N_NODES 100000
#define N_EDGES 3200000
#define WINDOW  200

// ---------------- scratch (no allocations allowed) ----------------
__device__ unsigned int d_he[N_NODES];    // encoded h (order-preserving uint)
__device__ unsigned int d_pre[N_NODES];   // encoded max over incoming h[src]
__device__ unsigned int d_suc[N_NODES];   // encoded max over outgoing h[dst]
__device__ float        d_e[N_NODES];     // exp(x)
__device__ double       d_gsum;           // softmax denominator

// Order-preserving float <-> uint mapping (total order == float order).
// enc of any finite float is > 0, so 0u works as the "no message" sentinel.
__device__ __forceinline__ unsigned int encf(float f) {
    unsigned int b = __float_as_uint(f);
    return (b & 0x80000000u) ? ~b : (b | 0x80000000u);
}
__device__ __forceinline__ float decf(unsigned int u) {
    return (u & 0x80000000u) ? __uint_as_float(u ^ 0x80000000u)
                             : __uint_as_float(~u);
}

// ---------------- K1: he[n] = enc(dot(loss[n,:200], W)); + scratch reset ---
// One warp per node; rows are 800B (16B aligned) -> float4 loads.
__global__ void k_series(const float* __restrict__ loss,
                         const float* __restrict__ W) {
    __shared__ float4 sW[WINDOW / 4];            // 50 float4
    int t   = threadIdx.x;
    int gid = blockIdx.x * blockDim.x + t;

    // fold scratch reset into this kernel (runs before k_edges / k_combine)
    if (gid < N_NODES) { d_pre[gid] = 0u; d_suc[gid] = 0u; }
    if (gid == 0)      { d_gsum = 0.0; }

    if (t < WINDOW / 4) sW[t] = ((const float4*)W)[t];
    __syncthreads();

    int node = gid >> 5;
    int lane = t & 31;
    if (node >= N_NODES) return;

    const float4* row = (const float4*)(loss + (size_t)node * WINDOW);
    float s = 0.f;
    #pragma unroll
    for (int j = lane; j < WINDOW / 4; j += 32) {
        float4 a = row[j];
        float4 w = sW[j];
        s += a.x * w.x + a.y * w.y + a.z * w.z + a.w * w.w;
    }
    #pragma unroll
    for (int o = 16; o; o >>= 1) s += __shfl_xor_sync(0xffffffffu, s, o);
    if (lane == 0) d_he[node] = encf(s);
}

// ---------------- K2: segment-max via filtered encoded atomicMax ----------
// d_pre/d_suc are monotonically non-decreasing, so a plain (possibly stale,
// therefore <= current) load safely filters atomics that cannot change the
// result. Stale data only makes the filter less effective, never wrong.
__global__ void k_edges(const int* __restrict__ src,
                        const int* __restrict__ dst) {
    int i = blockIdx.x * blockDim.x + threadIdx.x;
    if (i >= N_EDGES / 4) return;
    int4 s4 = ((const int4*)src)[i];
    int4 d4 = ((const int4*)dst)[i];

    #pragma unroll
    for (int k = 0; k < 4; k++) {
        int s = (k == 0) ? s4.x : (k == 1) ? s4.y : (k == 2) ? s4.z : s4.w;
        int d = (k == 0) ? d4.x : (k == 1) ? d4.y : (k == 2) ? d4.z : d4.w;
        if (s != d) {
            unsigned int hs = __ldg(&d_he[s]);
            unsigned int hd = __ldg(&d_he[d]);
            if (hs > d_pre[d]) atomicMax(&d_pre[d], hs);   // RED when needed
            if (hd > d_suc[s]) atomicMax(&d_suc[s], hd);
        }
    }
}

// ---------------- K3: combine + exp + block-reduced global sum -------------
// x = h + Wg0*pre + Wg1*suc is bounded (|x| ~< 1): softmax needs no max pass.
__global__ void k_combine(const float* __restrict__ Wg) {
    __shared__ float ssum[8];
    int i = blockIdx.x * blockDim.x + threadIdx.x;
    float e = 0.f;
    if (i < N_NODES) {
        unsigned int p = d_pre[i], s = d_suc[i];
        float pf = p ? decf(p) : 0.f;
        float sf = s ? decf(s) : 0.f;
        float x = decf(d_he[i]) + Wg[0] * pf + Wg[1] * sf;
        e = __expf(x);
        d_e[i] = e;
    }

    float v = e;
    #pragma unroll
    for (int o = 16; o; o >>= 1) v += __shfl_xor_sync(0xffffffffu, v, o);
    int lane = threadIdx.x & 31, wid = threadIdx.x >> 5;
    if (lane == 0) ssum[wid] = v;
    __syncthreads();
    if (wid == 0) {
        v = (lane < 8) ? ssum[lane] : 0.f;
        #pragma unroll
        for (int o = 4; o; o >>= 1) v += __shfl_xor_sync(0xffffffffu, v, o);
        if (lane == 0) atomicAdd(&d_gsum, (double)v);
    }
}

// ---------------- K4: normalize (float reciprocal, no FP64 divide) ---------
__global__ void k_out(float* __restrict__ out) {
    float inv = __fdividef(1.0f, (float)d_gsum);
    int i = blockIdx.x * blockDim.x + threadIdx.x;
    if (i < N_NODES) out[i] = d_e[i] * inv;
}

// ---------------- launch ----------------------------------------------------
extern "C" void kernel_launch(void* const* d_in, const int* in_sizes, int n_in,
                              void* d_out, int out_size) {
    const float* loss = (const float*)d_in[0];
    const float* Ws   = (const float*)d_in[1];
    const float* Wg   = (const float*)d_in[2];
    const int*   src  = (const int*)  d_in[3];
    const int*   dst  = (const int*)  d_in[4];
    float*       out  = (float*)d_out;

    const int B = 256;
    k_series <<<(N_NODES * 32 + B - 1) / B, B>>>(loss, Ws);
    k_edges  <<<(N_EDGES / 4 + B - 1) / B, B>>>(src, dst);
    k_combine<<<(N_NODES + B - 1) / B, B>>>(Wg);
    k_out    <<<(N_NODES + B - 1) / B, B>>>(out);
}

// round 8
// speedup vs baseline: 1.0186x; 1.0186x over previous
#include <cuda_runtime.h>
#include <math.h>

#define N_NODES 100000
#define N_EDGES 3200000
#define WINDOW  200

// ---------------- scratch (no allocations allowed) ----------------
__device__ unsigned int d_he[N_NODES];    // encoded h (order-preserving uint)
__device__ unsigned int d_pre[N_NODES];   // encoded max over incoming h[src]
__device__ unsigned int d_suc[N_NODES];   // encoded max over outgoing h[dst]
__device__ float        d_e[N_NODES];     // exp(x)
__device__ double       d_gsum;           // softmax denominator

// Order-preserving float <-> uint mapping (total order == float order).
// enc of any finite float is > 0, so 0u works as the "no message" sentinel.
__device__ __forceinline__ unsigned int encf(float f) {
    unsigned int b = __float_as_uint(f);
    return (b & 0x80000000u) ? ~b : (b | 0x80000000u);
}
__device__ __forceinline__ float decf(unsigned int u) {
    return (u & 0x80000000u) ? __uint_as_float(u ^ 0x80000000u)
                             : __uint_as_float(~u);
}

// ---------------- K1: he[n] = enc(dot(loss[n,:200], W)); + scratch reset ---
// One warp per node; rows are 800B (16B aligned) -> float4 loads.
__global__ void k_series(const float* __restrict__ loss,
                         const float* __restrict__ W) {
    __shared__ float4 sW[WINDOW / 4];            // 50 float4
    int t   = threadIdx.x;
    int gid = blockIdx.x * blockDim.x + t;

    // fold scratch reset into this kernel (runs before k_edges / k_combine)
    if (gid < N_NODES) { d_pre[gid] = 0u; d_suc[gid] = 0u; }
    if (gid == 0)      { d_gsum = 0.0; }

    if (t < WINDOW / 4) sW[t] = ((const float4*)W)[t];
    __syncthreads();

    int node = gid >> 5;
    int lane = t & 31;
    if (node >= N_NODES) return;

    const float4* row = (const float4*)(loss + (size_t)node * WINDOW);
    float s = 0.f;
    #pragma unroll
    for (int j = lane; j < WINDOW / 4; j += 32) {
        float4 a = row[j];
        float4 w = sW[j];
        s += a.x * w.x + a.y * w.y + a.z * w.z + a.w * w.w;
    }
    #pragma unroll
    for (int o = 16; o; o >>= 1) s += __shfl_xor_sync(0xffffffffu, s, o);
    if (lane == 0) d_he[node] = encf(s);
}

// ---------------- K2: segment-max via unconditional encoded atomicMax -----
// Fire-and-forget RED (no return use) is cheaper than any read-filtered
// variant on B300: the filter's L2 round-trip costs more than the RED.
__global__ void k_edges(const int* __restrict__ src,
                        const int* __restrict__ dst) {
    int i = blockIdx.x * blockDim.x + threadIdx.x;
    if (i >= N_EDGES / 4) return;
    int4 s4 = ((const int4*)src)[i];
    int4 d4 = ((const int4*)dst)[i];

    #pragma unroll
    for (int k = 0; k < 4; k++) {
        int s = (k == 0) ? s4.x : (k == 1) ? s4.y : (k == 2) ? s4.z : s4.w;
        int d = (k == 0) ? d4.x : (k == 1) ? d4.y : (k == 2) ? d4.z : d4.w;
        if (s != d) {
            unsigned int hs = __ldg(&d_he[s]);
            unsigned int hd = __ldg(&d_he[d]);
            atomicMax(&d_pre[d], hs);   // no return use -> RED
            atomicMax(&d_suc[s], hd);
        }
    }
}

// ---------------- K3: combine + exp + block-reduced global sum -------------
// x = h + Wg0*pre + Wg1*suc is bounded (|x| ~< 1): softmax needs no max pass.
__global__ void k_combine(const float* __restrict__ Wg) {
    __shared__ float ssum[8];
    int i = blockIdx.x * blockDim.x + threadIdx.x;
    float e = 0.f;
    if (i < N_NODES) {
        unsigned int p = d_pre[i], s = d_suc[i];
        float pf = p ? decf(p) : 0.f;
        float sf = s ? decf(s) : 0.f;
        float x = decf(d_he[i]) + Wg[0] * pf + Wg[1] * sf;
        e = __expf(x);
        d_e[i] = e;
    }

    float v = e;
    #pragma unroll
    for (int o = 16; o; o >>= 1) v += __shfl_xor_sync(0xffffffffu, v, o);
    int lane = threadIdx.x & 31, wid = threadIdx.x >> 5;
    if (lane == 0) ssum[wid] = v;
    __syncthreads();
    if (wid == 0) {
        v = (lane < 8) ? ssum[lane] : 0.f;
        #pragma unroll
        for (int o = 4; o; o >>= 1) v += __shfl_xor_sync(0xffffffffu, v, o);
        if (lane == 0) atomicAdd(&d_gsum, (double)v);
    }
}

// ---------------- K4: normalize (float reciprocal, no FP64 divide) ---------
__global__ void k_out(float* __restrict__ out) {
    float inv = __fdividef(1.0f, (float)d_gsum);
    int i = blockIdx.x * blockDim.x + threadIdx.x;
    if (i < N_NODES) out[i] = d_e[i] * inv;
}

// ---------------- launch ----------------------------------------------------
extern "C" void kernel_launch(void* const* d_in, const int* in_sizes, int n_in,
                              void* d_out, int out_size) {
    const float* loss = (const float*)d_in[0];
    const float* Ws   = (const float*)d_in[1];
    const float* Wg   = (const float*)d_in[2];
    const int*   src  = (const int*)  d_in[3];
    const int*   dst  = (const int*)  d_in[4];
    float*       out  = (float*)d_out;

    const int B = 256;
    k_series <<<(N_NODES * 32 + B - 1) / B, B>>>(loss, Ws);
    k_edges  <<<(N_EDGES / 4 + B - 1) / B, B>>>(src, dst);
    k_combine<<<(N_NODES + B - 1) / B, B>>>(Wg);
    k_out    <<<(N_NODES + B - 1) / B, B>>>(out);
}

// round 9
// speedup vs baseline: 1.0588x; 1.0395x over previous
#include <cuda_runtime.h>
#include <math.h>

#define N_NODES 100000
#define N_EDGES 3200000
#define WINDOW  200

// ---------------- scratch (no allocations allowed) ----------------
__device__ unsigned int d_he[N_NODES];    // encoded h (order-preserving uint)
__device__ unsigned int d_pre[N_NODES];   // encoded max over incoming h[src]
__device__ unsigned int d_suc[N_NODES];   // encoded max over outgoing h[dst]
__device__ float        d_e[N_NODES];     // exp(x)
__device__ double       d_gsum;           // softmax denominator

// Order-preserving float <-> uint mapping (total order == float order).
// enc of any finite float is > 0, so 0u works as the "no message" sentinel.
__device__ __forceinline__ unsigned int encf(float f) {
    unsigned int b = __float_as_uint(f);
    return (b & 0x80000000u) ? ~b : (b | 0x80000000u);
}
__device__ __forceinline__ float decf(unsigned int u) {
    return (u & 0x80000000u) ? __uint_as_float(u ^ 0x80000000u)
                             : __uint_as_float(~u);
}

// ---------------- K1: he[n] = enc(dot(loss[n,:200], W)); + scratch reset ---
// One warp per node; rows are 800B (16B aligned) -> float4 loads.
__global__ void k_series(const float* __restrict__ loss,
                         const float* __restrict__ W) {
    __shared__ float4 sW[WINDOW / 4];            // 50 float4
    int t   = threadIdx.x;
    int gid = blockIdx.x * blockDim.x + t;

    // fold scratch reset into this kernel (runs before k_edges / k_combine)
    if (gid < N_NODES) { d_pre[gid] = 0u; d_suc[gid] = 0u; }
    if (gid == 0)      { d_gsum = 0.0; }

    if (t < WINDOW / 4) sW[t] = ((const float4*)W)[t];
    __syncthreads();

    int node = gid >> 5;
    int lane = t & 31;
    if (node >= N_NODES) return;

    const float4* row = (const float4*)(loss + (size_t)node * WINDOW);
    float s = 0.f;
    #pragma unroll
    for (int j = lane; j < WINDOW / 4; j += 32) {
        float4 a = row[j];
        float4 w = sW[j];
        s += a.x * w.x + a.y * w.y + a.z * w.z + a.w * w.w;
    }
    #pragma unroll
    for (int o = 16; o; o >>= 1) s += __shfl_xor_sync(0xffffffffu, s, o);
    if (lane == 0) d_he[node] = encf(s);
}

// ---------------- K2: segment-max via branchless encoded atomicMax --------
// Front-batch all 8 gathers (MLP=8), then fire 8 REDs. Self-loops write the
// neutral sentinel 0u (never wins) instead of branching.
__global__ void k_edges(const int* __restrict__ src,
                        const int* __restrict__ dst) {
    int i = blockIdx.x * blockDim.x + threadIdx.x;
    if (i >= N_EDGES / 4) return;
    int4 s4 = ((const int4*)src)[i];
    int4 d4 = ((const int4*)dst)[i];
    int ss[4] = {s4.x, s4.y, s4.z, s4.w};
    int dd[4] = {d4.x, d4.y, d4.z, d4.w};

    unsigned int hs[4], hd[4];
    #pragma unroll
    for (int k = 0; k < 4; k++) {
        hs[k] = __ldg(&d_he[ss[k]]);
        hd[k] = __ldg(&d_he[dd[k]]);
    }
    #pragma unroll
    for (int k = 0; k < 4; k++) {
        bool ok = (ss[k] != dd[k]);
        atomicMax(&d_pre[dd[k]], ok ? hs[k] : 0u);   // no return use -> RED
        atomicMax(&d_suc[ss[k]], ok ? hd[k] : 0u);
    }
}

// ---------------- K3: combine + exp + block-reduced global sum (x4 vec) ----
// x = h + Wg0*pre + Wg1*suc is bounded (|x| ~< 1): softmax needs no max pass.
// N_NODES % 4 == 0: each thread handles 4 nodes via uint4/float4.
__global__ void k_combine(const float* __restrict__ Wg) {
    __shared__ float ssum[8];
    int i = blockIdx.x * blockDim.x + threadIdx.x;   // group of 4 nodes
    float v = 0.f;
    float w0 = Wg[0], w1 = Wg[1];
    if (i < N_NODES / 4) {
        uint4 p4 = ((const uint4*)d_pre)[i];
        uint4 s4 = ((const uint4*)d_suc)[i];
        uint4 h4 = ((const uint4*)d_he)[i];
        float4 e4;
        {
            unsigned int pp[4] = {p4.x, p4.y, p4.z, p4.w};
            unsigned int sc[4] = {s4.x, s4.y, s4.z, s4.w};
            unsigned int hh[4] = {h4.x, h4.y, h4.z, h4.w};
            float* e = (float*)&e4;
            #pragma unroll
            for (int k = 0; k < 4; k++) {
                float pf = pp[k] ? decf(pp[k]) : 0.f;
                float sf = sc[k] ? decf(sc[k]) : 0.f;
                float x  = decf(hh[k]) + w0 * pf + w1 * sf;
                e[k] = __expf(x);
                v += e[k];
            }
        }
        ((float4*)d_e)[i] = e4;
    }

    #pragma unroll
    for (int o = 16; o; o >>= 1) v += __shfl_xor_sync(0xffffffffu, v, o);
    int lane = threadIdx.x & 31, wid = threadIdx.x >> 5;
    if (lane == 0) ssum[wid] = v;
    __syncthreads();
    if (wid == 0) {
        v = (lane < 8) ? ssum[lane] : 0.f;
        #pragma unroll
        for (int o = 4; o; o >>= 1) v += __shfl_xor_sync(0xffffffffu, v, o);
        if (lane == 0) atomicAdd(&d_gsum, (double)v);
    }
}

// ---------------- K4: normalize (float recip, float4) ----------------------
__global__ void k_out(float* __restrict__ out) {
    float inv = __fdividef(1.0f, (float)d_gsum);
    int i = blockIdx.x * blockDim.x + threadIdx.x;
    if (i < N_NODES / 4) {
        float4 e = ((const float4*)d_e)[i];
        e.x *= inv; e.y *= inv; e.z *= inv; e.w *= inv;
        ((float4*)out)[i] = e;
    }
}

// ---------------- launch ----------------------------------------------------
extern "C" void kernel_launch(void* const* d_in, const int* in_sizes, int n_in,
                              void* d_out, int out_size) {
    const float* loss = (const float*)d_in[0];
    const float* Ws   = (const float*)d_in[1];
    const float* Wg   = (const float*)d_in[2];
    const int*   src  = (const int*)  d_in[3];
    const int*   dst  = (const int*)  d_in[4];
    float*       out  = (float*)d_out;

    const int B = 256;
    k_series <<<(N_NODES * 32 + B - 1) / B, B>>>(loss, Ws);
    k_edges  <<<(N_EDGES / 4 + B - 1) / B, B>>>(src, dst);
    k_combine<<<(N_NODES / 4 + B - 1) / B, B>>>(Wg);
    k_out    <<<(N_NODES / 4 + B - 1) / B, B>>>(out);
}

// round 10
// speedup vs baseline: 1.0842x; 1.0240x over previous
#include <cuda_runtime.h>
#include <math.h>

#define N_NODES 100000
#define N_EDGES 3200000
#define WINDOW  200

// ---------------- scratch (no allocations allowed) ----------------
__device__ unsigned int d_he[N_NODES];    // encoded h (order-preserving uint)
__device__ unsigned int d_pre[N_NODES];   // encoded max over incoming h[src]
__device__ unsigned int d_suc[N_NODES];   // encoded max over outgoing h[dst]
__device__ float        d_e[N_NODES];     // exp(x)
__device__ double       d_gsum;           // softmax denominator

// Order-preserving float <-> uint mapping (total order == float order).
// enc of any finite float is > 0, so 0u works as the "no message" sentinel.
__device__ __forceinline__ unsigned int encf(float f) {
    unsigned int b = __float_as_uint(f);
    return (b & 0x80000000u) ? ~b : (b | 0x80000000u);
}
__device__ __forceinline__ float decf(unsigned int u) {
    return (u & 0x80000000u) ? __uint_as_float(u ^ 0x80000000u)
                             : __uint_as_float(~u);
}

// ---------------- K1: he[n] = enc(dot(loss[n,:200], W)); + scratch reset ---
// One warp per node; rows are 800B (16B aligned) -> float4 loads.
__global__ void k_series(const float* __restrict__ loss,
                         const float* __restrict__ W) {
    __shared__ float4 sW[WINDOW / 4];            // 50 float4
    int t   = threadIdx.x;
    int gid = blockIdx.x * blockDim.x + t;

    // fold scratch reset into this kernel (runs before k_edges / k_combine)
    if (gid < N_NODES) { d_pre[gid] = 0u; d_suc[gid] = 0u; }
    if (gid == 0)      { d_gsum = 0.0; }

    if (t < WINDOW / 4) sW[t] = ((const float4*)W)[t];
    __syncthreads();

    int node = gid >> 5;
    int lane = t & 31;
    if (node >= N_NODES) return;

    const float4* row = (const float4*)(loss + (size_t)node * WINDOW);
    float s = 0.f;
    #pragma unroll
    for (int j = lane; j < WINDOW / 4; j += 32) {
        float4 a = row[j];
        float4 w = sW[j];
        s += a.x * w.x + a.y * w.y + a.z * w.z + a.w * w.w;
    }
    #pragma unroll
    for (int o = 16; o; o >>= 1) s += __shfl_xor_sync(0xffffffffu, s, o);
    if (lane == 0) d_he[node] = encf(s);
}

// ---------------- K2: segment-max via branchless encoded atomicMax --------
// 8 edges per thread. Front-batch all 16 gathers (MLP=16), then fire 16
// fire-and-forget REDs. Self-loops write the neutral sentinel 0u.
__global__ void k_edges(const int* __restrict__ src,
                        const int* __restrict__ dst) {
    int i = blockIdx.x * blockDim.x + threadIdx.x;   // group of 8 edges
    if (i >= N_EDGES / 8) return;

    int4 sa = ((const int4*)src)[2 * i];
    int4 sb = ((const int4*)src)[2 * i + 1];
    int4 da = ((const int4*)dst)[2 * i];
    int4 db = ((const int4*)dst)[2 * i + 1];
    int ss[8] = {sa.x, sa.y, sa.z, sa.w, sb.x, sb.y, sb.z, sb.w};
    int dd[8] = {da.x, da.y, da.z, da.w, db.x, db.y, db.z, db.w};

    unsigned int hs[8], hd[8];
    #pragma unroll
    for (int k = 0; k < 8; k++) hs[k] = __ldg(&d_he[ss[k]]);
    #pragma unroll
    for (int k = 0; k < 8; k++) hd[k] = __ldg(&d_he[dd[k]]);

    #pragma unroll
    for (int k = 0; k < 8; k++) {
        bool ok = (ss[k] != dd[k]);
        atomicMax(&d_pre[dd[k]], ok ? hs[k] : 0u);   // no return use -> RED
        atomicMax(&d_suc[ss[k]], ok ? hd[k] : 0u);
    }
}

// ---------------- K3: combine + exp + block-reduced global sum (x4 vec) ----
// x = h + Wg0*pre + Wg1*suc is bounded (|x| ~< 1): softmax needs no max pass.
// N_NODES % 4 == 0: each thread handles 4 nodes via uint4/float4.
__global__ void k_combine(const float* __restrict__ Wg) {
    __shared__ float ssum[16];
    int i = blockIdx.x * blockDim.x + threadIdx.x;   // group of 4 nodes
    float v = 0.f;
    float w0 = Wg[0], w1 = Wg[1];
    if (i < N_NODES / 4) {
        uint4 p4 = ((const uint4*)d_pre)[i];
        uint4 s4 = ((const uint4*)d_suc)[i];
        uint4 h4 = ((const uint4*)d_he)[i];
        float4 e4;
        {
            unsigned int pp[4] = {p4.x, p4.y, p4.z, p4.w};
            unsigned int sc[4] = {s4.x, s4.y, s4.z, s4.w};
            unsigned int hh[4] = {h4.x, h4.y, h4.z, h4.w};
            float* e = (float*)&e4;
            #pragma unroll
            for (int k = 0; k < 4; k++) {
                float pf = pp[k] ? decf(pp[k]) : 0.f;
                float sf = sc[k] ? decf(sc[k]) : 0.f;
                float x  = decf(hh[k]) + w0 * pf + w1 * sf;
                e[k] = __expf(x);
                v += e[k];
            }
        }
        ((float4*)d_e)[i] = e4;
    }

    #pragma unroll
    for (int o = 16; o; o >>= 1) v += __shfl_xor_sync(0xffffffffu, v, o);
    int lane = threadIdx.x & 31, wid = threadIdx.x >> 5;
    int nw = blockDim.x >> 5;
    if (lane == 0) ssum[wid] = v;
    __syncthreads();
    if (wid == 0) {
        v = (lane < nw) ? ssum[lane] : 0.f;
        #pragma unroll
        for (int o = 8; o; o >>= 1) v += __shfl_xor_sync(0xffffffffu, v, o);
        if (lane == 0) atomicAdd(&d_gsum, (double)v);
    }
}

// ---------------- K4: normalize (float recip, float4) ----------------------
__global__ void k_out(float* __restrict__ out) {
    float inv = __fdividef(1.0f, (float)d_gsum);
    int i = blockIdx.x * blockDim.x + threadIdx.x;
    if (i < N_NODES / 4) {
        float4 e = ((const float4*)d_e)[i];
        e.x *= inv; e.y *= inv; e.z *= inv; e.w *= inv;
        ((float4*)out)[i] = e;
    }
}

// ---------------- launch ----------------------------------------------------
extern "C" void kernel_launch(void* const* d_in, const int* in_sizes, int n_in,
                              void* d_out, int out_size) {
    const float* loss = (const float*)d_in[0];
    const float* Ws   = (const float*)d_in[1];
    const float* Wg   = (const float*)d_in[2];
    const int*   src  = (const int*)  d_in[3];
    const int*   dst  = (const int*)  d_in[4];
    float*       out  = (float*)d_out;

    k_series <<<(N_NODES * 32 + 255) / 256, 256>>>(loss, Ws);
    k_edges  <<<(N_EDGES / 8 + 255) / 256, 256>>>(src, dst);
    k_combine<<<(N_NODES / 4 + 511) / 512, 512>>>(Wg);
    k_out    <<<(N_NODES / 4 + 255) / 256, 256>>>(out);
}